// round 14
// baseline (speedup 1.0000x reference)
#include <cuda_runtime.h>
#include <cstdint>

#define ULL unsigned long long
#define CAP 4096
#define BIN_CTAS 64
#define MAXT 33000

__device__ float4   g_pack[1000 * 48];  // {bz+Gz, br+Gr, Gh, h_prev} per (slot,u)
__device__ int      g_winner[1000];
__device__ int      g_count[1000];
__device__ int      g_tbase[1001];
__device__ int      g_tslot[MAXT];      // packed (s<<13)|(loc<<5)|nrows
__device__ int      g_perm[1000 * CAP];
__device__ uint32_t g_xs[(size_t)MAXT * 1024]; // per tile: 4 ktiles x (128 hi + 128 lo)
__device__ uint4    g_WB[21 * 4 * 32];  // B frags: {b0hi,b1hi,b0lo,b1lo}

__device__ __forceinline__ ULL pk2(float lo, float hi) {
    ULL r; asm("mov.b64 %0, {%1, %2};" : "=l"(r) : "f"(lo), "f"(hi)); return r;
}
__device__ __forceinline__ float2 up2(ULL v) {
    float2 r; asm("mov.b64 {%0, %1}, %2;" : "=f"(r.x), "=f"(r.y) : "l"(v)); return r;
}
__device__ __forceinline__ ULL fma2(ULL a, ULL b, ULL c) {
    ULL d; asm("fma.rn.f32x2 %0, %1, %2, %3;" : "=l"(d) : "l"(a), "l"(b), "l"(c)); return d;
}
__device__ __forceinline__ uint32_t tf32r(float f) {
    uint32_t r; asm("cvt.rna.tf32.f32 %0, %1;" : "=r"(r) : "f"(f)); return r;
}
__device__ __forceinline__ float sigmoidf(float x) {
    return __fdividef(1.0f, 1.0f + __expf(-x));
}
__device__ __forceinline__ float tanh_fast(float x) {
    return fmaf(2.0f, __fdividef(1.0f, 1.0f + __expf(-2.0f * x)), -1.0f);
}

#define MMA(d, a, b0, b1)                                                     \
    asm volatile("mma.sync.aligned.m16n8k8.row.col.f32.tf32.tf32.f32 "        \
                 "{%0,%1,%2,%3},{%4,%5,%6,%7},{%8,%9},{%0,%1,%2,%3};"         \
                 : "+f"((d)[0]), "+f"((d)[1]), "+f"((d)[2]), "+f"((d)[3])     \
                 : "r"((a).x), "r"((a).y), "r"((a).z), "r"((a).w),            \
                   "r"(b0), "r"(b1))

// ---------- kernel 0: prep(0..999) + Wpack(1000) + binning(1001..) ----------
__global__ void __launch_bounds__(256)
setup_kernel(const float* __restrict__ state, const float* __restrict__ Urec,
             float* __restrict__ out_state, const float* __restrict__ gbias,
             const float* __restrict__ Wk, const float* __restrict__ Dw,
             const int* __restrict__ ids, int B) {
    const int tid = threadIdx.x;
    if (blockIdx.x < 1000) {
        const int s = blockIdx.x;
        __shared__ float hs[48];
        __shared__ float gt[144];
        if (tid < 48) {
            float v = state[s * 48 + tid];
            hs[tid] = v;
            out_state[s * 48 + tid] = v;
        }
        if (tid == 0) { g_winner[s] = -1; g_count[s] = 0; }
        __syncthreads();
        if (tid < 144) {
            float acc = 0.0f;
            #pragma unroll
            for (int u = 0; u < 48; u++)
                acc = fmaf(hs[u], Urec[u * 144 + tid], acc);
            if (tid < 96) acc += gbias[tid];
            gt[tid] = acc;
        }
        __syncthreads();
        if (tid < 48)
            g_pack[s * 48 + tid] = make_float4(gt[tid], gt[48 + tid], gt[96 + tid], hs[tid]);
    } else if (blockIdx.x == 1000) {
        for (int idx = tid; idx < 21 * 4 * 32; idx += 256) {
            int nt = idx >> 7, kt = (idx >> 5) & 3, lane = idx & 31;
            int g = lane >> 2, t = lane & 3;
            int n = nt * 8 + g, k0 = kt * 8 + t, k1 = k0 + 4;
            float w0 = (n < 144) ? Wk[k0 * 144 + n] : Dw[k0 * 24 + (n - 144)];
            float w1 = (n < 144) ? Wk[k1 * 144 + n] : Dw[k1 * 24 + (n - 144)];
            uint4 o;
            o.x = tf32r(w0); o.y = tf32r(w1);
            o.z = tf32r(w0 - __uint_as_float(o.x));
            o.w = tf32r(w1 - __uint_as_float(o.y));
            g_WB[idx] = o;
        }
    } else {
        __shared__ int lcnt[1000], lmax[1000], lbase[1000];
        const int cta = blockIdx.x - 1001;
        const int per = (B + BIN_CTAS - 1) / BIN_CTAS;
        const int lo = cta * per, hi = min(B, lo + per);
        for (int s = tid; s < 1000; s += 256) { lcnt[s] = 0; lmax[s] = -1; }
        __syncthreads();
        for (int b = lo + tid; b < hi; b += 256) {
            int id = ids[b];
            atomicAdd(&lcnt[id], 1);
            atomicMax(&lmax[id], b);
        }
        __syncthreads();
        for (int s = tid; s < 1000; s += 256) {
            int c = lcnt[s];
            if (c > 0) {
                lbase[s] = atomicAdd(&g_count[s], c);
                atomicMax(&g_winner[s], lmax[s]);
                lcnt[s] = 0;
            }
        }
        __syncthreads();
        for (int b = lo + tid; b < hi; b += 256) {
            int id = ids[b];
            int off = atomicAdd(&lcnt[id], 1);
            int pos = lbase[id] + off;
            if (pos < CAP) g_perm[id * CAP + pos] = b;
        }
    }
}

// ---------- kernel 1: scan of tile counts ----------
__global__ void scan_kernel() {
    __shared__ int tmp[1024];
    int t = threadIdx.x;
    int v = (t < 1000) ? ((min(g_count[t], CAP) + 15) >> 4) : 0;
    tmp[t] = v;
    __syncthreads();
    #pragma unroll
    for (int off = 1; off < 1024; off <<= 1) {
        int u = 0;
        if (t >= off) u = tmp[t - off];
        __syncthreads();
        if (t >= off) tmp[t] += u;
        __syncthreads();
    }
    if (t <= 1000) g_tbase[t] = tmp[t] - ((t < 1000) ? v : 0);
}

// ---------- kernel 2: tile -> (slot, loc, nrows) map ----------
__global__ void __launch_bounds__(32)
tmap_kernel() {
    const int s = blockIdx.x;
    const int cnt = min(g_count[s], CAP);
    const int tb = g_tbase[s];
    const int nt = g_tbase[s + 1] - tb;
    for (int t = threadIdx.x; t < nt; t += 32) {
        int nrows = min(cnt - t * 16, 16);
        g_tslot[tb + t] = (s << 13) | (t << 5) | nrows;
    }
}

// ---------- kernel 3: tile-parallel stage into A-frag order (tf32 hi/lo) ----------
__global__ void __launch_bounds__(128)
stage_kernel(const float* __restrict__ inputs) {
    const int tile = blockIdx.x;
    if (tile >= g_tbase[1000]) return;
    __shared__ uint32_t buf[1024];
    const int v = g_tslot[tile];
    const int nrows = v & 31, loc = (v >> 5) & 255, s = v >> 13;
    const int* pbase = g_perm + s * CAP + loc * 16;
    const int tid = threadIdx.x;
    const int r = tid >> 3, c4 = tid & 7;
    int b = (r < nrows) ? pbase[r] : -1;
    float4 x = make_float4(0.f, 0.f, 0.f, 0.f);
    if (b >= 0) x = *(const float4*)(inputs + (size_t)b * 32 + c4 * 4);
    const float* vp = &x.x;
    #pragma unroll
    for (int cc = 0; cc < 4; cc++) {
        int col = c4 * 4 + cc;
        int kt = col >> 3, t = col & 3, ch = (col >> 2) & 1;
        int lane = (r & 7) * 4 + t;
        int i = (ch << 1) | (r >> 3);
        uint32_t hi = tf32r(vp[cc]);
        uint32_t lo = tf32r(vp[cc] - __uint_as_float(hi));
        buf[kt * 256 + lane * 4 + i] = hi;
        buf[kt * 256 + 128 + lane * 4 + i] = lo;
    }
    __syncthreads();
    uint4* dst = (uint4*)(g_xs + (size_t)tile * 1024);
    const uint4* src = (const uint4*)buf;
    dst[tid] = src[tid];
    dst[tid + 128] = src[tid + 128];
}

// ---------- kernel 4: main — tensor-core GRU + head (R12 structure) ----------
__global__ void __launch_bounds__(128)
main_kernel(const float* __restrict__ gbias,
            const float* __restrict__ Dw, const float* __restrict__ Db,
            const float* __restrict__ Ow, const float* __restrict__ Ob,
            float* __restrict__ out, float* __restrict__ out_state) {
    __shared__ float sDh[48 * 24];
    __shared__ float hsA[4][16 * 52];
    const int tid = threadIdx.x;
    for (int i = tid; i < 48 * 24; i += 128) sDh[i] = Dw[768 + i];
    __syncthreads();

    const int wid = tid >> 5, lane = tid & 31;
    const int g = lane >> 2, t = lane & 3;
    float* hrow = hsA[wid];
    const int total = g_tbase[1000];
    const float ob = Ob[0];

    float2 bh2[6];
    #pragma unroll
    for (int j = 0; j < 6; j++)
        bh2[j] = *(const float2*)(gbias + 96 + 8 * j + 2 * t);

    for (int tile = blockIdx.x * 4 + wid; tile < total; tile += gridDim.x * 4) {
        const int v = g_tslot[tile];
        const int nrows = v & 31, loc = (v >> 5) & 255, s = v >> 13;
        const int* pbase = g_perm + s * CAP + loc * 16;
        const int bA = (g < nrows) ? pbase[g] : -1;
        const int bB = (g + 8 < nrows) ? pbase[g + 8] : -1;

        const uint32_t* xa = g_xs + (size_t)tile * 1024;
        uint4 Ah[4], Al[4];
        #pragma unroll
        for (int kt = 0; kt < 4; kt++) {
            Ah[kt] = *(const uint4*)(xa + kt * 256 + lane * 4);
            Al[kt] = *(const uint4*)(xa + kt * 256 + 128 + lane * 4);
        }

        float acc[21][4];
        #pragma unroll
        for (int n = 0; n < 21; n++) { acc[n][0] = acc[n][1] = acc[n][2] = acc[n][3] = 0.f; }

        #pragma unroll
        for (int nt = 0; nt < 21; nt++)
            #pragma unroll
            for (int kt = 0; kt < 4; kt++) {
                uint4 wb = g_WB[(nt * 4 + kt) * 32 + lane];
                MMA(acc[nt], Ah[kt], wb.x, wb.y);
                MMA(acc[nt], Ah[kt], wb.z, wb.w);
                MMA(acc[nt], Al[kt], wb.x, wb.y);
            }

        const float4* pk = g_pack + s * 48;
        #pragma unroll
        for (int j = 0; j < 6; j++) {
            float4 fa = pk[8 * j + 2 * t];
            float4 fb = pk[8 * j + 2 * t + 1];
            int u0 = 8 * j + 2 * t;
            {
                float z0 = sigmoidf(acc[j][0] + fa.x);
                float r0 = sigmoidf(acc[j + 6][0] + fa.y);
                float h0 = z0 * fa.w + (1.f - z0) * tanh_fast(acc[j + 12][0] + bh2[j].x + r0 * fa.z);
                float z1 = sigmoidf(acc[j][2] + fa.x);
                float r1 = sigmoidf(acc[j + 6][2] + fa.y);
                float h1 = z1 * fa.w + (1.f - z1) * tanh_fast(acc[j + 12][2] + bh2[j].x + r1 * fa.z);
                hrow[g * 52 + u0] = h0;
                hrow[(g + 8) * 52 + u0] = h1;
            }
            {
                float z0 = sigmoidf(acc[j][1] + fb.x);
                float r0 = sigmoidf(acc[j + 6][1] + fb.y);
                float h0 = z0 * fb.w + (1.f - z0) * tanh_fast(acc[j + 12][1] + bh2[j].y + r0 * fb.z);
                float z1 = sigmoidf(acc[j][3] + fb.x);
                float r1 = sigmoidf(acc[j + 6][3] + fb.y);
                float h1 = z1 * fb.w + (1.f - z1) * tanh_fast(acc[j + 12][3] + bh2[j].y + r1 * fb.z);
                hrow[g * 52 + u0 + 1] = h0;
                hrow[(g + 8) * 52 + u0 + 1] = h1;
            }
        }
        __syncwarp();

        ULL hg[3], hh[3];
        #pragma unroll
        for (int m = 0; m < 3; m++) {
            hg[m] = pk2(acc[18 + m][0], acc[18 + m][1]);
            hh[m] = pk2(acc[18 + m][2], acc[18 + m][3]);
        }
        for (int u = 0; u < 48; u++) {
            float h0 = hrow[g * 52 + u], h1 = hrow[(g + 8) * 52 + u];
            ULL b0 = pk2(h0, h0), b1 = pk2(h1, h1);
            #pragma unroll
            for (int m = 0; m < 3; m++) {
                ULL w = *(const ULL*)(sDh + u * 24 + 8 * m + 2 * t);
                hg[m] = fma2(b0, w, hg[m]);
                hh[m] = fma2(b1, w, hh[m]);
            }
        }

        float o0 = 0.f, o1 = 0.f;
        #pragma unroll
        for (int m = 0; m < 3; m++) {
            int c = 8 * m + 2 * t;
            float d0 = Db[c], d1 = Db[c + 1], w0 = Ow[c], w1 = Ow[c + 1];
            float2 a = up2(hg[m]), bq = up2(hh[m]);
            o0 = fmaf(fmaxf(a.x + d0, 0.f), w0, o0);
            o0 = fmaf(fmaxf(a.y + d1, 0.f), w1, o0);
            o1 = fmaf(fmaxf(bq.x + d0, 0.f), w0, o1);
            o1 = fmaf(fmaxf(bq.y + d1, 0.f), w1, o1);
        }
        o0 += __shfl_xor_sync(0xffffffffu, o0, 1);
        o0 += __shfl_xor_sync(0xffffffffu, o0, 2);
        o1 += __shfl_xor_sync(0xffffffffu, o1, 1);
        o1 += __shfl_xor_sync(0xffffffffu, o1, 2);
        if (t == 0) {
            if (bA >= 0) out[bA] = sigmoidf(o0 + ob);
            if (bB >= 0) out[bB] = sigmoidf(o1 + ob);
        }

        const int win = g_winner[s];
        if (win >= 0 && t == 0) {
            if (bA == win || bB == win) {
                int r = (bA == win) ? g : g + 8;
                float4* os = (float4*)(out_state + s * 48);
                const float4* hr = (const float4*)(hrow + r * 52);
                #pragma unroll
                for (int m = 0; m < 12; m++) os[m] = hr[m];
            }
        }
        __syncwarp();
    }
}

extern "C" void kernel_launch(void* const* d_in, const int* in_sizes, int n_in,
                              void* d_out, int out_size) {
    const float* inputs = (const float*)d_in[0];
    const int*   ids    = (const int*)d_in[1];
    const float* state  = (const float*)d_in[2];
    const float* Wk     = (const float*)d_in[3];
    const float* Urec   = (const float*)d_in[4];
    const float* gbias  = (const float*)d_in[5];
    const float* Dw     = (const float*)d_in[6];
    const float* Db     = (const float*)d_in[7];
    const float* Ow     = (const float*)d_in[8];
    const float* Ob     = (const float*)d_in[9];

    const int B = in_sizes[0] / 32;
    const int S = in_sizes[2] / 48;

    float* out       = (float*)d_out;
    float* out_state = out + B;

    setup_kernel<<<S + 1 + BIN_CTAS, 256>>>(state, Urec, out_state, gbias, Wk, Dw, ids, B);
    scan_kernel<<<1, 1024>>>();
    tmap_kernel<<<S, 32>>>();
    stage_kernel<<<32500, 128>>>(inputs);
    main_kernel<<<740, 128>>>(gbias, Dw, Db, Ow, Ob, out, out_state);
}

// round 15
// speedup vs baseline: 1.2772x; 1.2772x over previous
#include <cuda_runtime.h>
#include <cstdint>

#define ULL unsigned long long
#define CAP 4096
#define BIN_CTAS 64
#define MAXT 33000

__device__ float4   g_pack[1000 * 48];  // {bz+Gz, br+Gr, Gh, h_prev} per (slot,u)
__device__ int      g_winner[1000];
__device__ int      g_count[1000];
__device__ int      g_tbase[1001];
__device__ int      g_tslot[MAXT];      // packed (s<<13)|(loc<<5)|nrows
__device__ int      g_perm[1000 * CAP];
__device__ uint4    g_WB[21 * 4 * 32];  // B frags: {b0hi,b1hi,b0lo,b1lo}

__device__ __forceinline__ ULL pk2(float lo, float hi) {
    ULL r; asm("mov.b64 %0, {%1, %2};" : "=l"(r) : "f"(lo), "f"(hi)); return r;
}
__device__ __forceinline__ float2 up2(ULL v) {
    float2 r; asm("mov.b64 {%0, %1}, %2;" : "=f"(r.x), "=f"(r.y) : "l"(v)); return r;
}
__device__ __forceinline__ ULL fma2(ULL a, ULL b, ULL c) {
    ULL d; asm("fma.rn.f32x2 %0, %1, %2, %3;" : "=l"(d) : "l"(a), "l"(b), "l"(c)); return d;
}
__device__ __forceinline__ uint32_t tf32r(float f) {
    uint32_t r; asm("cvt.rna.tf32.f32 %0, %1;" : "=r"(r) : "f"(f)); return r;
}
__device__ __forceinline__ float sigmoidf(float x) {
    return __fdividef(1.0f, 1.0f + __expf(-x));
}
__device__ __forceinline__ float tanh_fast(float x) {
    return fmaf(2.0f, __fdividef(1.0f, 1.0f + __expf(-2.0f * x)), -1.0f);
}

#define MMA(d, a, b0, b1)                                                     \
    asm volatile("mma.sync.aligned.m16n8k8.row.col.f32.tf32.tf32.f32 "        \
                 "{%0,%1,%2,%3},{%4,%5,%6,%7},{%8,%9},{%0,%1,%2,%3};"         \
                 : "+f"((d)[0]), "+f"((d)[1]), "+f"((d)[2]), "+f"((d)[3])     \
                 : "r"((a).x), "r"((a).y), "r"((a).z), "r"((a).w),            \
                   "r"(b0), "r"(b1))

// ---------- kernel 0: prep(0..999) + Wpack(1000) + binning(1001..) ----------
__global__ void __launch_bounds__(256)
setup_kernel(const float* __restrict__ state, const float* __restrict__ Urec,
             float* __restrict__ out_state, const float* __restrict__ gbias,
             const float* __restrict__ Wk, const float* __restrict__ Dw,
             const int* __restrict__ ids, int B) {
    const int tid = threadIdx.x;
    if (blockIdx.x < 1000) {
        const int s = blockIdx.x;
        __shared__ float hs[48];
        __shared__ float gt[144];
        if (tid < 48) {
            float v = state[s * 48 + tid];
            hs[tid] = v;
            out_state[s * 48 + tid] = v;
        }
        if (tid == 0) { g_winner[s] = -1; g_count[s] = 0; }
        __syncthreads();
        if (tid < 144) {
            float acc = 0.0f;
            #pragma unroll
            for (int u = 0; u < 48; u++)
                acc = fmaf(hs[u], Urec[u * 144 + tid], acc);
            if (tid < 96) acc += gbias[tid];
            gt[tid] = acc;
        }
        __syncthreads();
        if (tid < 48)
            g_pack[s * 48 + tid] = make_float4(gt[tid], gt[48 + tid], gt[96 + tid], hs[tid]);
    } else if (blockIdx.x == 1000) {
        for (int idx = tid; idx < 21 * 4 * 32; idx += 256) {
            int nt = idx >> 7, kt = (idx >> 5) & 3, lane = idx & 31;
            int g = lane >> 2, t = lane & 3;
            int n = nt * 8 + g, k0 = kt * 8 + t, k1 = k0 + 4;
            float w0 = (n < 144) ? Wk[k0 * 144 + n] : Dw[k0 * 24 + (n - 144)];
            float w1 = (n < 144) ? Wk[k1 * 144 + n] : Dw[k1 * 24 + (n - 144)];
            uint4 o;
            o.x = tf32r(w0); o.y = tf32r(w1);
            o.z = tf32r(w0 - __uint_as_float(o.x));
            o.w = tf32r(w1 - __uint_as_float(o.y));
            g_WB[idx] = o;
        }
    } else {
        __shared__ int lcnt[1000], lmax[1000], lbase[1000];
        const int cta = blockIdx.x - 1001;
        const int per = (B + BIN_CTAS - 1) / BIN_CTAS;
        const int lo = cta * per, hi = min(B, lo + per);
        for (int s = tid; s < 1000; s += 256) { lcnt[s] = 0; lmax[s] = -1; }
        __syncthreads();
        for (int b = lo + tid; b < hi; b += 256) {
            int id = ids[b];
            atomicAdd(&lcnt[id], 1);
            atomicMax(&lmax[id], b);
        }
        __syncthreads();
        for (int s = tid; s < 1000; s += 256) {
            int c = lcnt[s];
            if (c > 0) {
                lbase[s] = atomicAdd(&g_count[s], c);
                atomicMax(&g_winner[s], lmax[s]);
                lcnt[s] = 0;
            }
        }
        __syncthreads();
        for (int b = lo + tid; b < hi; b += 256) {
            int id = ids[b];
            int off = atomicAdd(&lcnt[id], 1);
            int pos = lbase[id] + off;
            if (pos < CAP) g_perm[id * CAP + pos] = b;
        }
    }
}

// ---------- kernel 1: scan of tile counts ----------
__global__ void scan_kernel() {
    __shared__ int tmp[1024];
    int t = threadIdx.x;
    int v = (t < 1000) ? ((min(g_count[t], CAP) + 15) >> 4) : 0;
    tmp[t] = v;
    __syncthreads();
    #pragma unroll
    for (int off = 1; off < 1024; off <<= 1) {
        int u = 0;
        if (t >= off) u = tmp[t - off];
        __syncthreads();
        if (t >= off) tmp[t] += u;
        __syncthreads();
    }
    if (t <= 1000) g_tbase[t] = tmp[t] - ((t < 1000) ? v : 0);
}

// ---------- kernel 2: tile -> (slot, loc, nrows) map ----------
__global__ void __launch_bounds__(32)
tmap_kernel() {
    const int s = blockIdx.x;
    const int cnt = min(g_count[s], CAP);
    const int tb = g_tbase[s];
    const int nt = g_tbase[s + 1] - tb;
    for (int t = threadIdx.x; t < nt; t += 32) {
        int nrows = min(cnt - t * 16, 16);
        g_tslot[tb + t] = (s << 13) | (t << 5) | nrows;
    }
}

// ---------- kernel 3: main — tensor-core GRU + head, in-warp staging ----------
__global__ void __launch_bounds__(128)
main_kernel(const float* __restrict__ inputs, const float* __restrict__ gbias,
            const float* __restrict__ Dw, const float* __restrict__ Db,
            const float* __restrict__ Ow, const float* __restrict__ Ob,
            float* __restrict__ out, float* __restrict__ out_state) {
    __shared__ float sDh[48 * 24];
    __shared__ float hsA[4][16 * 52];
    __shared__ __align__(16) float xbuf[4][16 * 36];   // padded rows: conflict-free frag reads
    const int tid = threadIdx.x;
    for (int i = tid; i < 48 * 24; i += 128) sDh[i] = Dw[768 + i];
    __syncthreads();

    const int wid = tid >> 5, lane = tid & 31;
    const int g = lane >> 2, t = lane & 3;
    float* hrow = hsA[wid];
    float* xb   = xbuf[wid];
    const int total = g_tbase[1000];
    const float ob = Ob[0];

    float2 bh2[6];
    #pragma unroll
    for (int j = 0; j < 6; j++)
        bh2[j] = *(const float2*)(gbias + 96 + 8 * j + 2 * t);

    for (int tile = blockIdx.x * 4 + wid; tile < total; tile += gridDim.x * 4) {
        const int v = g_tslot[tile];
        const int nrows = v & 31, loc = (v >> 5) & 255, s = v >> 13;
        const int* pbase = g_perm + s * CAP + loc * 16;

        // in-warp stage: coalesced row loads (each row = one 128B line) -> padded smem
        __syncwarp();
        {
            const int c4 = lane & 7;
            #pragma unroll
            for (int it = 0; it < 4; it++) {
                int row = it * 4 + (lane >> 3);
                int b = (row < nrows) ? pbase[row] : -1;
                float4 x = make_float4(0.f, 0.f, 0.f, 0.f);
                if (b >= 0) x = *(const float4*)(inputs + (size_t)b * 32 + c4 * 4);
                *(float4*)(xb + row * 36 + c4 * 4) = x;
            }
        }
        __syncwarp();

        // A fragments from smem (conflict-free LDS.32), tf32 hi/lo in regs
        uint4 Ah[4], Al[4];
        #pragma unroll
        for (int kt = 0; kt < 4; kt++) {
            float v0 = xb[g * 36 + kt * 8 + t];
            float v1 = xb[(g + 8) * 36 + kt * 8 + t];
            float v2 = xb[g * 36 + kt * 8 + t + 4];
            float v3 = xb[(g + 8) * 36 + kt * 8 + t + 4];
            Ah[kt].x = tf32r(v0); Al[kt].x = tf32r(v0 - __uint_as_float(Ah[kt].x));
            Ah[kt].y = tf32r(v1); Al[kt].y = tf32r(v1 - __uint_as_float(Ah[kt].y));
            Ah[kt].z = tf32r(v2); Al[kt].z = tf32r(v2 - __uint_as_float(Ah[kt].z));
            Ah[kt].w = tf32r(v3); Al[kt].w = tf32r(v3 - __uint_as_float(Ah[kt].w));
        }

        const int bA = (g < nrows) ? pbase[g] : -1;
        const int bB = (g + 8 < nrows) ? pbase[g + 8] : -1;

        float acc[21][4];
        #pragma unroll
        for (int n = 0; n < 21; n++) { acc[n][0] = acc[n][1] = acc[n][2] = acc[n][3] = 0.f; }

        #pragma unroll
        for (int nt = 0; nt < 21; nt++)
            #pragma unroll
            for (int kt = 0; kt < 4; kt++) {
                uint4 wb = g_WB[(nt * 4 + kt) * 32 + lane];
                MMA(acc[nt], Ah[kt], wb.x, wb.y);
                MMA(acc[nt], Ah[kt], wb.z, wb.w);
                MMA(acc[nt], Al[kt], wb.x, wb.y);
            }

        const float4* pk = g_pack + s * 48;
        #pragma unroll
        for (int j = 0; j < 6; j++) {
            float4 fa = pk[8 * j + 2 * t];
            float4 fb = pk[8 * j + 2 * t + 1];
            int u0 = 8 * j + 2 * t;
            {
                float z0 = sigmoidf(acc[j][0] + fa.x);
                float r0 = sigmoidf(acc[j + 6][0] + fa.y);
                float h0 = z0 * fa.w + (1.f - z0) * tanh_fast(acc[j + 12][0] + bh2[j].x + r0 * fa.z);
                float z1 = sigmoidf(acc[j][2] + fa.x);
                float r1 = sigmoidf(acc[j + 6][2] + fa.y);
                float h1 = z1 * fa.w + (1.f - z1) * tanh_fast(acc[j + 12][2] + bh2[j].x + r1 * fa.z);
                hrow[g * 52 + u0] = h0;
                hrow[(g + 8) * 52 + u0] = h1;
            }
            {
                float z0 = sigmoidf(acc[j][1] + fb.x);
                float r0 = sigmoidf(acc[j + 6][1] + fb.y);
                float h0 = z0 * fb.w + (1.f - z0) * tanh_fast(acc[j + 12][1] + bh2[j].y + r0 * fb.z);
                float z1 = sigmoidf(acc[j][3] + fb.x);
                float r1 = sigmoidf(acc[j + 6][3] + fb.y);
                float h1 = z1 * fb.w + (1.f - z1) * tanh_fast(acc[j + 12][3] + bh2[j].y + r1 * fb.z);
                hrow[g * 52 + u0 + 1] = h0;
                hrow[(g + 8) * 52 + u0 + 1] = h1;
            }
        }
        __syncwarp();

        ULL hg[3], hh[3];
        #pragma unroll
        for (int m = 0; m < 3; m++) {
            hg[m] = pk2(acc[18 + m][0], acc[18 + m][1]);
            hh[m] = pk2(acc[18 + m][2], acc[18 + m][3]);
        }
        for (int u = 0; u < 48; u++) {
            float h0 = hrow[g * 52 + u], h1 = hrow[(g + 8) * 52 + u];
            ULL b0 = pk2(h0, h0), b1 = pk2(h1, h1);
            #pragma unroll
            for (int m = 0; m < 3; m++) {
                ULL w = *(const ULL*)(sDh + u * 24 + 8 * m + 2 * t);
                hg[m] = fma2(b0, w, hg[m]);
                hh[m] = fma2(b1, w, hh[m]);
            }
        }

        float o0 = 0.f, o1 = 0.f;
        #pragma unroll
        for (int m = 0; m < 3; m++) {
            int c = 8 * m + 2 * t;
            float d0 = Db[c], d1 = Db[c + 1], w0 = Ow[c], w1 = Ow[c + 1];
            float2 a = up2(hg[m]), bq = up2(hh[m]);
            o0 = fmaf(fmaxf(a.x + d0, 0.f), w0, o0);
            o0 = fmaf(fmaxf(a.y + d1, 0.f), w1, o0);
            o1 = fmaf(fmaxf(bq.x + d0, 0.f), w0, o1);
            o1 = fmaf(fmaxf(bq.y + d1, 0.f), w1, o1);
        }
        o0 += __shfl_xor_sync(0xffffffffu, o0, 1);
        o0 += __shfl_xor_sync(0xffffffffu, o0, 2);
        o1 += __shfl_xor_sync(0xffffffffu, o1, 1);
        o1 += __shfl_xor_sync(0xffffffffu, o1, 2);
        if (t == 0) {
            if (bA >= 0) out[bA] = sigmoidf(o0 + ob);
            if (bB >= 0) out[bB] = sigmoidf(o1 + ob);
        }

        const int win = g_winner[s];
        if (win >= 0 && t == 0) {
            if (bA == win || bB == win) {
                int r = (bA == win) ? g : g + 8;
                float4* os = (float4*)(out_state + s * 48);
                const float4* hr = (const float4*)(hrow + r * 52);
                #pragma unroll
                for (int m = 0; m < 12; m++) os[m] = hr[m];
            }
        }
        __syncwarp();
    }
}

extern "C" void kernel_launch(void* const* d_in, const int* in_sizes, int n_in,
                              void* d_out, int out_size) {
    const float* inputs = (const float*)d_in[0];
    const int*   ids    = (const int*)d_in[1];
    const float* state  = (const float*)d_in[2];
    const float* Wk     = (const float*)d_in[3];
    const float* Urec   = (const float*)d_in[4];
    const float* gbias  = (const float*)d_in[5];
    const float* Dw     = (const float*)d_in[6];
    const float* Db     = (const float*)d_in[7];
    const float* Ow     = (const float*)d_in[8];
    const float* Ob     = (const float*)d_in[9];

    const int B = in_sizes[0] / 32;
    const int S = in_sizes[2] / 48;

    float* out       = (float*)d_out;
    float* out_state = out + B;

    setup_kernel<<<S + 1 + BIN_CTAS, 256>>>(state, Urec, out_state, gbias, Wk, Dw, ids, B);
    scan_kernel<<<1, 1024>>>();
    tmap_kernel<<<S, 32>>>();
    main_kernel<<<740, 128>>>(inputs, gbias, Dw, Db, Ow, Ob, out, out_state);
}

// round 16
// speedup vs baseline: 1.3760x; 1.0774x over previous
#include <cuda_runtime.h>
#include <cstdint>

#define ULL unsigned long long
#define CAP 4096
#define BIN_CTAS 64
#define MAXT 33000

__device__ float4   g_pack[1000 * 48];  // {bz+Gz, br+Gr, Gh, h_prev} per (slot,u)
__device__ int      g_winner[1000];
__device__ int      g_count[1000];
__device__ int      g_tbase[1001];
__device__ int      g_tslot[MAXT];      // packed (s<<13)|(loc<<5)|nrows
__device__ int      g_perm[1000 * CAP];
__device__ uint4    g_WB[21 * 4 * 32];  // B frags: {b0hi,b1hi,b0lo,b1lo}

__device__ __forceinline__ ULL pk2(float lo, float hi) {
    ULL r; asm("mov.b64 %0, {%1, %2};" : "=l"(r) : "f"(lo), "f"(hi)); return r;
}
__device__ __forceinline__ float2 up2(ULL v) {
    float2 r; asm("mov.b64 {%0, %1}, %2;" : "=f"(r.x), "=f"(r.y) : "l"(v)); return r;
}
__device__ __forceinline__ ULL fma2(ULL a, ULL b, ULL c) {
    ULL d; asm("fma.rn.f32x2 %0, %1, %2, %3;" : "=l"(d) : "l"(a), "l"(b), "l"(c)); return d;
}
__device__ __forceinline__ uint32_t tf32r(float f) {
    uint32_t r; asm("cvt.rna.tf32.f32 %0, %1;" : "=r"(r) : "f"(f)); return r;
}
__device__ __forceinline__ float sigmoidf(float x) {
    return __fdividef(1.0f, 1.0f + __expf(-x));
}
__device__ __forceinline__ float tanh_fast(float x) {
    return fmaf(2.0f, __fdividef(1.0f, 1.0f + __expf(-2.0f * x)), -1.0f);
}

#define MMA(d, a, b0, b1)                                                     \
    asm volatile("mma.sync.aligned.m16n8k8.row.col.f32.tf32.tf32.f32 "        \
                 "{%0,%1,%2,%3},{%4,%5,%6,%7},{%8,%9},{%0,%1,%2,%3};"         \
                 : "+f"((d)[0]), "+f"((d)[1]), "+f"((d)[2]), "+f"((d)[3])     \
                 : "r"((a).x), "r"((a).y), "r"((a).z), "r"((a).w),            \
                   "r"(b0), "r"(b1))

// ---------- kernel 0: prep(0..999) + Wpack(1000) + binning(1001..) ----------
__global__ void __launch_bounds__(256)
setup_kernel(const float* __restrict__ state, const float* __restrict__ Urec,
             float* __restrict__ out_state, const float* __restrict__ gbias,
             const float* __restrict__ Wk, const float* __restrict__ Dw,
             const int* __restrict__ ids, int B) {
    const int tid = threadIdx.x;
    if (blockIdx.x < 1000) {
        const int s = blockIdx.x;
        __shared__ float hs[48];
        __shared__ float gt[144];
        if (tid < 48) {
            float v = state[s * 48 + tid];
            hs[tid] = v;
            out_state[s * 48 + tid] = v;
        }
        if (tid == 0) { g_winner[s] = -1; g_count[s] = 0; }
        __syncthreads();
        if (tid < 144) {
            float acc = 0.0f;
            #pragma unroll
            for (int u = 0; u < 48; u++)
                acc = fmaf(hs[u], Urec[u * 144 + tid], acc);
            if (tid < 96) acc += gbias[tid];
            gt[tid] = acc;
        }
        __syncthreads();
        if (tid < 48)
            g_pack[s * 48 + tid] = make_float4(gt[tid], gt[48 + tid], gt[96 + tid], hs[tid]);
    } else if (blockIdx.x == 1000) {
        for (int idx = tid; idx < 21 * 4 * 32; idx += 256) {
            int nt = idx >> 7, kt = (idx >> 5) & 3, lane = idx & 31;
            int g = lane >> 2, t = lane & 3;
            int n = nt * 8 + g, k0 = kt * 8 + t, k1 = k0 + 4;
            float w0 = (n < 144) ? Wk[k0 * 144 + n] : Dw[k0 * 24 + (n - 144)];
            float w1 = (n < 144) ? Wk[k1 * 144 + n] : Dw[k1 * 24 + (n - 144)];
            uint4 o;
            o.x = tf32r(w0); o.y = tf32r(w1);
            o.z = tf32r(w0 - __uint_as_float(o.x));
            o.w = tf32r(w1 - __uint_as_float(o.y));
            g_WB[idx] = o;
        }
    } else {
        __shared__ int lcnt[1000], lmax[1000], lbase[1000];
        const int cta = blockIdx.x - 1001;
        const int per = (B + BIN_CTAS - 1) / BIN_CTAS;
        const int lo = cta * per, hi = min(B, lo + per);
        for (int s = tid; s < 1000; s += 256) { lcnt[s] = 0; lmax[s] = -1; }
        __syncthreads();
        for (int b = lo + tid; b < hi; b += 256) {
            int id = ids[b];
            atomicAdd(&lcnt[id], 1);
            atomicMax(&lmax[id], b);
        }
        __syncthreads();
        for (int s = tid; s < 1000; s += 256) {
            int c = lcnt[s];
            if (c > 0) {
                lbase[s] = atomicAdd(&g_count[s], c);
                atomicMax(&g_winner[s], lmax[s]);
                lcnt[s] = 0;
            }
        }
        __syncthreads();
        for (int b = lo + tid; b < hi; b += 256) {
            int id = ids[b];
            int off = atomicAdd(&lcnt[id], 1);
            int pos = lbase[id] + off;
            if (pos < CAP) g_perm[id * CAP + pos] = b;
        }
    }
}

// ---------- kernel 1: scan of tile counts ----------
__global__ void scan_kernel() {
    __shared__ int tmp[1024];
    int t = threadIdx.x;
    int v = (t < 1000) ? ((min(g_count[t], CAP) + 15) >> 4) : 0;
    tmp[t] = v;
    __syncthreads();
    #pragma unroll
    for (int off = 1; off < 1024; off <<= 1) {
        int u = 0;
        if (t >= off) u = tmp[t - off];
        __syncthreads();
        if (t >= off) tmp[t] += u;
        __syncthreads();
    }
    if (t <= 1000) g_tbase[t] = tmp[t] - ((t < 1000) ? v : 0);
}

// ---------- kernel 2: tile -> (slot, loc, nrows) map ----------
__global__ void __launch_bounds__(32)
tmap_kernel() {
    const int s = blockIdx.x;
    const int cnt = min(g_count[s], CAP);
    const int tb = g_tbase[s];
    const int nt = g_tbase[s + 1] - tb;
    for (int t = threadIdx.x; t < nt; t += 32) {
        int nrows = min(cnt - t * 16, 16);
        g_tslot[tb + t] = (s << 13) | (t << 5) | nrows;
    }
}

// ---------- kernel 3: main — tensor-core GRU + head, in-warp staging, j-grouped ----------
__global__ void __launch_bounds__(128)
main_kernel(const float* __restrict__ inputs, const float* __restrict__ gbias,
            const float* __restrict__ Dw, const float* __restrict__ Db,
            const float* __restrict__ Ow, const float* __restrict__ Ob,
            float* __restrict__ out, float* __restrict__ out_state) {
    __shared__ float sDh[48 * 24];
    __shared__ float hsA[4][16 * 52];
    __shared__ __align__(16) float xbuf[4][16 * 36];   // padded rows: conflict-free frag reads
    const int tid = threadIdx.x;
    for (int i = tid; i < 48 * 24; i += 128) sDh[i] = Dw[768 + i];
    __syncthreads();

    const int wid = tid >> 5, lane = tid & 31;
    const int g = lane >> 2, t = lane & 3;
    float* hrow = hsA[wid];
    float* xb   = xbuf[wid];
    const int total = g_tbase[1000];
    const float ob = Ob[0];
    const float2* gb2 = (const float2*)(gbias + 96);

    for (int tile = blockIdx.x * 4 + wid; tile < total; tile += gridDim.x * 4) {
        const int v = g_tslot[tile];
        const int nrows = v & 31, loc = (v >> 5) & 255, s = v >> 13;
        const int* pbase = g_perm + s * CAP + loc * 16;

        // in-warp stage: coalesced row loads (each row = one 128B line) -> padded smem
        __syncwarp();
        {
            const int c4 = lane & 7;
            #pragma unroll
            for (int it = 0; it < 4; it++) {
                int row = it * 4 + (lane >> 3);
                int b = (row < nrows) ? pbase[row] : -1;
                float4 x = make_float4(0.f, 0.f, 0.f, 0.f);
                if (b >= 0) x = *(const float4*)(inputs + (size_t)b * 32 + c4 * 4);
                *(float4*)(xb + row * 36 + c4 * 4) = x;
            }
        }
        __syncwarp();

        // A fragments from smem (conflict-free LDS.32), tf32 hi/lo in regs
        uint4 Ah[4], Al[4];
        #pragma unroll
        for (int kt = 0; kt < 4; kt++) {
            float v0 = xb[g * 36 + kt * 8 + t];
            float v1 = xb[(g + 8) * 36 + kt * 8 + t];
            float v2 = xb[g * 36 + kt * 8 + t + 4];
            float v3 = xb[(g + 8) * 36 + kt * 8 + t + 4];
            Ah[kt].x = tf32r(v0); Al[kt].x = tf32r(v0 - __uint_as_float(Ah[kt].x));
            Ah[kt].y = tf32r(v1); Al[kt].y = tf32r(v1 - __uint_as_float(Ah[kt].y));
            Ah[kt].z = tf32r(v2); Al[kt].z = tf32r(v2 - __uint_as_float(Ah[kt].z));
            Ah[kt].w = tf32r(v3); Al[kt].w = tf32r(v3 - __uint_as_float(Ah[kt].w));
        }

        const int bA = (g < nrows) ? pbase[g] : -1;
        const int bB = (g + 8 < nrows) ? pbase[g + 8] : -1;
        const float4* pk = g_pack + s * 48;

        // gate groups: nt in {j, j+6, j+12}, only 12 live accumulators
        #pragma unroll
        for (int j = 0; j < 6; j++) {
            float4 fa = pk[8 * j + 2 * t];
            float4 fb = pk[8 * j + 2 * t + 1];
            float2 bh = gb2[4 * j + t];
            float az[4] = {fa.x, fb.x, fa.x, fb.x};
            float ar[4] = {fa.y, fb.y, fa.y, fb.y};
            float ah[4] = {bh.x, bh.y, bh.x, bh.y};
            #pragma unroll
            for (int kt = 0; kt < 4; kt++) {
                uint4 wz = g_WB[(j * 4 + kt) * 32 + lane];
                uint4 wr = g_WB[((j + 6) * 4 + kt) * 32 + lane];
                uint4 wh = g_WB[((j + 12) * 4 + kt) * 32 + lane];
                MMA(az, Ah[kt], wz.x, wz.y); MMA(az, Ah[kt], wz.z, wz.w); MMA(az, Al[kt], wz.x, wz.y);
                MMA(ar, Ah[kt], wr.x, wr.y); MMA(ar, Ah[kt], wr.z, wr.w); MMA(ar, Al[kt], wr.x, wr.y);
                MMA(ah, Ah[kt], wh.x, wh.y); MMA(ah, Ah[kt], wh.z, wh.w); MMA(ah, Al[kt], wh.x, wh.y);
            }
            const int u0 = 8 * j + 2 * t;
            {
                float z0 = sigmoidf(az[0]);
                float r0 = sigmoidf(ar[0]);
                float h0 = z0 * fa.w + (1.f - z0) * tanh_fast(ah[0] + r0 * fa.z);
                float z1 = sigmoidf(az[2]);
                float r1 = sigmoidf(ar[2]);
                float h1 = z1 * fa.w + (1.f - z1) * tanh_fast(ah[2] + r1 * fa.z);
                hrow[g * 52 + u0] = h0;
                hrow[(g + 8) * 52 + u0] = h1;
            }
            {
                float z0 = sigmoidf(az[1]);
                float r0 = sigmoidf(ar[1]);
                float h0 = z0 * fb.w + (1.f - z0) * tanh_fast(ah[1] + r0 * fb.z);
                float z1 = sigmoidf(az[3]);
                float r1 = sigmoidf(ar[3]);
                float h1 = z1 * fb.w + (1.f - z1) * tanh_fast(ah[3] + r1 * fb.z);
                hrow[g * 52 + u0 + 1] = h0;
                hrow[(g + 8) * 52 + u0 + 1] = h1;
            }
        }
        __syncwarp();

        // head x-part: nt 18..20 (12 accumulators)
        float hx0[4] = {0, 0, 0, 0}, hx1[4] = {0, 0, 0, 0}, hx2[4] = {0, 0, 0, 0};
        #pragma unroll
        for (int kt = 0; kt < 4; kt++) {
            uint4 w0 = g_WB[(18 * 4 + kt) * 32 + lane];
            uint4 w1 = g_WB[(19 * 4 + kt) * 32 + lane];
            uint4 w2 = g_WB[(20 * 4 + kt) * 32 + lane];
            MMA(hx0, Ah[kt], w0.x, w0.y); MMA(hx0, Ah[kt], w0.z, w0.w); MMA(hx0, Al[kt], w0.x, w0.y);
            MMA(hx1, Ah[kt], w1.x, w1.y); MMA(hx1, Ah[kt], w1.z, w1.w); MMA(hx1, Al[kt], w1.x, w1.y);
            MMA(hx2, Ah[kt], w2.x, w2.y); MMA(hx2, Ah[kt], w2.z, w2.w); MMA(hx2, Al[kt], w2.x, w2.y);
        }

        ULL hg[3], hh[3];
        hg[0] = pk2(hx0[0], hx0[1]); hh[0] = pk2(hx0[2], hx0[3]);
        hg[1] = pk2(hx1[0], hx1[1]); hh[1] = pk2(hx1[2], hx1[3]);
        hg[2] = pk2(hx2[0], hx2[1]); hh[2] = pk2(hx2[2], hx2[3]);
        for (int u = 0; u < 48; u++) {
            float h0 = hrow[g * 52 + u], h1 = hrow[(g + 8) * 52 + u];
            ULL b0 = pk2(h0, h0), b1 = pk2(h1, h1);
            #pragma unroll
            for (int m = 0; m < 3; m++) {
                ULL w = *(const ULL*)(sDh + u * 24 + 8 * m + 2 * t);
                hg[m] = fma2(b0, w, hg[m]);
                hh[m] = fma2(b1, w, hh[m]);
            }
        }

        float o0 = 0.f, o1 = 0.f;
        #pragma unroll
        for (int m = 0; m < 3; m++) {
            int c = 8 * m + 2 * t;
            float d0 = Db[c], d1 = Db[c + 1], w0 = Ow[c], w1 = Ow[c + 1];
            float2 a = up2(hg[m]), bq = up2(hh[m]);
            o0 = fmaf(fmaxf(a.x + d0, 0.f), w0, o0);
            o0 = fmaf(fmaxf(a.y + d1, 0.f), w1, o0);
            o1 = fmaf(fmaxf(bq.x + d0, 0.f), w0, o1);
            o1 = fmaf(fmaxf(bq.y + d1, 0.f), w1, o1);
        }
        o0 += __shfl_xor_sync(0xffffffffu, o0, 1);
        o0 += __shfl_xor_sync(0xffffffffu, o0, 2);
        o1 += __shfl_xor_sync(0xffffffffu, o1, 1);
        o1 += __shfl_xor_sync(0xffffffffu, o1, 2);
        if (t == 0) {
            if (bA >= 0) out[bA] = sigmoidf(o0 + ob);
            if (bB >= 0) out[bB] = sigmoidf(o1 + ob);
        }

        const int win = g_winner[s];
        if (win >= 0 && t == 0) {
            if (bA == win || bB == win) {
                int r = (bA == win) ? g : g + 8;
                float4* os = (float4*)(out_state + s * 48);
                const float4* hr = (const float4*)(hrow + r * 52);
                #pragma unroll
                for (int m = 0; m < 12; m++) os[m] = hr[m];
            }
        }
        __syncwarp();
    }
}

extern "C" void kernel_launch(void* const* d_in, const int* in_sizes, int n_in,
                              void* d_out, int out_size) {
    const float* inputs = (const float*)d_in[0];
    const int*   ids    = (const int*)d_in[1];
    const float* state  = (const float*)d_in[2];
    const float* Wk     = (const float*)d_in[3];
    const float* Urec   = (const float*)d_in[4];
    const float* gbias  = (const float*)d_in[5];
    const float* Dw     = (const float*)d_in[6];
    const float* Db     = (const float*)d_in[7];
    const float* Ow     = (const float*)d_in[8];
    const float* Ob     = (const float*)d_in[9];

    const int B = in_sizes[0] / 32;
    const int S = in_sizes[2] / 48;

    float* out       = (float*)d_out;
    float* out_state = out + B;

    setup_kernel<<<S + 1 + BIN_CTAS, 256>>>(state, Urec, out_state, gbias, Wk, Dw, ids, B);
    scan_kernel<<<1, 1024>>>();
    tmap_kernel<<<S, 32>>>();
    main_kernel<<<592, 128>>>(inputs, gbias, Dw, Db, Ow, Ob, out, out_state);
}

// round 17
// speedup vs baseline: 1.6283x; 1.1834x over previous
#include <cuda_runtime.h>
#include <cstdint>

#define ULL unsigned long long
#define CAP 4096
#define BIN_CTAS 64
#define MAXT 33000

__device__ float4   g_pack[1000 * 48];  // {bz+Gz, br+Gr, Gh, h_prev} per (slot,u)
__device__ int      g_winner[1000];
__device__ int      g_count[1000];
__device__ int      g_tbase[1001];
__device__ int      g_tslot[MAXT];      // packed (s<<13)|(loc<<5)|nrows
__device__ int      g_perm[1000 * CAP];
__device__ uint4    g_WB[21 * 4 * 32];  // B frags: {b0hi,b1hi,b0lo,b1lo}

__device__ __forceinline__ ULL pk2(float lo, float hi) {
    ULL r; asm("mov.b64 %0, {%1, %2};" : "=l"(r) : "f"(lo), "f"(hi)); return r;
}
__device__ __forceinline__ float2 up2(ULL v) {
    float2 r; asm("mov.b64 {%0, %1}, %2;" : "=f"(r.x), "=f"(r.y) : "l"(v)); return r;
}
__device__ __forceinline__ ULL fma2(ULL a, ULL b, ULL c) {
    ULL d; asm("fma.rn.f32x2 %0, %1, %2, %3;" : "=l"(d) : "l"(a), "l"(b), "l"(c)); return d;
}
__device__ __forceinline__ uint32_t tf32r(float f) {
    uint32_t r; asm("cvt.rna.tf32.f32 %0, %1;" : "=r"(r) : "f"(f)); return r;
}
__device__ __forceinline__ float sigmoidf(float x) {
    return __fdividef(1.0f, 1.0f + __expf(-x));
}
__device__ __forceinline__ float tanh_fast(float x) {
    return fmaf(2.0f, __fdividef(1.0f, 1.0f + __expf(-2.0f * x)), -1.0f);
}

#define MMA(d, a, b0, b1)                                                     \
    asm volatile("mma.sync.aligned.m16n8k8.row.col.f32.tf32.tf32.f32 "        \
                 "{%0,%1,%2,%3},{%4,%5,%6,%7},{%8,%9},{%0,%1,%2,%3};"         \
                 : "+f"((d)[0]), "+f"((d)[1]), "+f"((d)[2]), "+f"((d)[3])     \
                 : "r"((a).x), "r"((a).y), "r"((a).z), "r"((a).w),            \
                   "r"(b0), "r"(b1))

// ---------- kernel 0: prep(0..999) + Wpack(1000) + binning(1001..) ----------
__global__ void __launch_bounds__(256)
setup_kernel(const float* __restrict__ state, const float* __restrict__ Urec,
             float* __restrict__ out_state, const float* __restrict__ gbias,
             const float* __restrict__ Wk, const float* __restrict__ Dw,
             const int* __restrict__ ids, int B) {
    const int tid = threadIdx.x;
    if (blockIdx.x < 1000) {
        const int s = blockIdx.x;
        __shared__ float hs[48];
        __shared__ float gt[144];
        if (tid < 48) {
            float v = state[s * 48 + tid];
            hs[tid] = v;
            out_state[s * 48 + tid] = v;
        }
        if (tid == 0) { g_winner[s] = -1; g_count[s] = 0; }
        __syncthreads();
        if (tid < 144) {
            float acc = 0.0f;
            #pragma unroll
            for (int u = 0; u < 48; u++)
                acc = fmaf(hs[u], Urec[u * 144 + tid], acc);
            if (tid < 96) acc += gbias[tid];
            gt[tid] = acc;
        }
        __syncthreads();
        if (tid < 48)
            g_pack[s * 48 + tid] = make_float4(gt[tid], gt[48 + tid], gt[96 + tid], hs[tid]);
    } else if (blockIdx.x == 1000) {
        for (int idx = tid; idx < 21 * 4 * 32; idx += 256) {
            int nt = idx >> 7, kt = (idx >> 5) & 3, lane = idx & 31;
            int g = lane >> 2, t = lane & 3;
            int n = nt * 8 + g, k0 = kt * 8 + t, k1 = k0 + 4;
            float w0 = (n < 144) ? Wk[k0 * 144 + n] : Dw[k0 * 24 + (n - 144)];
            float w1 = (n < 144) ? Wk[k1 * 144 + n] : Dw[k1 * 24 + (n - 144)];
            uint4 o;
            o.x = tf32r(w0); o.y = tf32r(w1);
            o.z = tf32r(w0 - __uint_as_float(o.x));
            o.w = tf32r(w1 - __uint_as_float(o.y));
            g_WB[idx] = o;
        }
    } else {
        __shared__ int lcnt[1000], lmax[1000], lbase[1000];
        const int cta = blockIdx.x - 1001;
        const int per = (B + BIN_CTAS - 1) / BIN_CTAS;
        const int lo = cta * per, hi = min(B, lo + per);
        for (int s = tid; s < 1000; s += 256) { lcnt[s] = 0; lmax[s] = -1; }
        __syncthreads();
        for (int b = lo + tid; b < hi; b += 256) {
            int id = ids[b];
            atomicAdd(&lcnt[id], 1);
            atomicMax(&lmax[id], b);
        }
        __syncthreads();
        for (int s = tid; s < 1000; s += 256) {
            int c = lcnt[s];
            if (c > 0) {
                lbase[s] = atomicAdd(&g_count[s], c);
                atomicMax(&g_winner[s], lmax[s]);
                lcnt[s] = 0;
            }
        }
        __syncthreads();
        for (int b = lo + tid; b < hi; b += 256) {
            int id = ids[b];
            int off = atomicAdd(&lcnt[id], 1);
            int pos = lbase[id] + off;
            if (pos < CAP) g_perm[id * CAP + pos] = b;
        }
    }
}

// ---------- kernel 1: scan of tile counts ----------
__global__ void scan_kernel() {
    __shared__ int tmp[1024];
    int t = threadIdx.x;
    int v = (t < 1000) ? ((min(g_count[t], CAP) + 15) >> 4) : 0;
    tmp[t] = v;
    __syncthreads();
    #pragma unroll
    for (int off = 1; off < 1024; off <<= 1) {
        int u = 0;
        if (t >= off) u = tmp[t - off];
        __syncthreads();
        if (t >= off) tmp[t] += u;
        __syncthreads();
    }
    if (t <= 1000) g_tbase[t] = tmp[t] - ((t < 1000) ? v : 0);
}

// ---------- kernel 2: tile -> (slot, loc, nrows) map ----------
__global__ void __launch_bounds__(32)
tmap_kernel() {
    const int s = blockIdx.x;
    const int cnt = min(g_count[s], CAP);
    const int tb = g_tbase[s];
    const int nt = g_tbase[s + 1] - tb;
    for (int t = threadIdx.x; t < nt; t += 32) {
        int nrows = min(cnt - t * 16, 16);
        g_tslot[tb + t] = (s << 13) | (t << 5) | nrows;
    }
}

// ---------- kernel 3: main — tensor-core GRU + head, in-warp staging, j-grouped ----------
__global__ void __launch_bounds__(128, 6)
main_kernel(const float* __restrict__ inputs, const float* __restrict__ gbias,
            const float* __restrict__ Dw, const float* __restrict__ Db,
            const float* __restrict__ Ow, const float* __restrict__ Ob,
            float* __restrict__ out, float* __restrict__ out_state) {
    __shared__ float sDh[48 * 24];
    __shared__ float hsA[4][16 * 52];
    __shared__ __align__(16) float xbuf[4][16 * 36];   // padded rows: conflict-free frag reads
    const int tid = threadIdx.x;
    for (int i = tid; i < 48 * 24; i += 128) sDh[i] = Dw[768 + i];
    __syncthreads();

    const int wid = tid >> 5, lane = tid & 31;
    const int g = lane >> 2, t = lane & 3;
    float* hrow = hsA[wid];
    float* xb   = xbuf[wid];
    const int total = g_tbase[1000];
    const float ob = Ob[0];
    const float2* gb2 = (const float2*)(gbias + 96);

    for (int tile = blockIdx.x * 4 + wid; tile < total; tile += gridDim.x * 4) {
        const int v = g_tslot[tile];
        const int nrows = v & 31, loc = (v >> 5) & 255, s = v >> 13;
        const int* pbase = g_perm + s * CAP + loc * 16;

        // in-warp stage: coalesced row loads (each row = one 128B line) -> padded smem
        __syncwarp();
        {
            const int c4 = lane & 7;
            #pragma unroll
            for (int it = 0; it < 4; it++) {
                int row = it * 4 + (lane >> 3);
                int b = (row < nrows) ? pbase[row] : -1;
                float4 x = make_float4(0.f, 0.f, 0.f, 0.f);
                if (b >= 0) x = *(const float4*)(inputs + (size_t)b * 32 + c4 * 4);
                *(float4*)(xb + row * 36 + c4 * 4) = x;
            }
        }
        __syncwarp();

        // A fragments from smem (conflict-free LDS.32), tf32 hi/lo in regs
        uint4 Ah[4], Al[4];
        #pragma unroll
        for (int kt = 0; kt < 4; kt++) {
            float v0 = xb[g * 36 + kt * 8 + t];
            float v1 = xb[(g + 8) * 36 + kt * 8 + t];
            float v2 = xb[g * 36 + kt * 8 + t + 4];
            float v3 = xb[(g + 8) * 36 + kt * 8 + t + 4];
            Ah[kt].x = tf32r(v0); Al[kt].x = tf32r(v0 - __uint_as_float(Ah[kt].x));
            Ah[kt].y = tf32r(v1); Al[kt].y = tf32r(v1 - __uint_as_float(Ah[kt].y));
            Ah[kt].z = tf32r(v2); Al[kt].z = tf32r(v2 - __uint_as_float(Ah[kt].z));
            Ah[kt].w = tf32r(v3); Al[kt].w = tf32r(v3 - __uint_as_float(Ah[kt].w));
        }

        const int bA = (g < nrows) ? pbase[g] : -1;
        const int bB = (g + 8 < nrows) ? pbase[g + 8] : -1;
        const float4* pk = g_pack + s * 48;

        // gate groups: nt in {j, j+6, j+12}, only 12 live accumulators
        #pragma unroll
        for (int j = 0; j < 6; j++) {
            float4 fa = pk[8 * j + 2 * t];
            float4 fb = pk[8 * j + 2 * t + 1];
            float2 bh = gb2[4 * j + t];
            float az[4] = {fa.x, fb.x, fa.x, fb.x};
            float ar[4] = {fa.y, fb.y, fa.y, fb.y};
            float ah[4] = {bh.x, bh.y, bh.x, bh.y};
            #pragma unroll
            for (int kt = 0; kt < 4; kt++) {
                uint4 wz = g_WB[(j * 4 + kt) * 32 + lane];
                uint4 wr = g_WB[((j + 6) * 4 + kt) * 32 + lane];
                uint4 wh = g_WB[((j + 12) * 4 + kt) * 32 + lane];
                MMA(az, Ah[kt], wz.x, wz.y); MMA(az, Ah[kt], wz.z, wz.w); MMA(az, Al[kt], wz.x, wz.y);
                MMA(ar, Ah[kt], wr.x, wr.y); MMA(ar, Ah[kt], wr.z, wr.w); MMA(ar, Al[kt], wr.x, wr.y);
                MMA(ah, Ah[kt], wh.x, wh.y); MMA(ah, Ah[kt], wh.z, wh.w); MMA(ah, Al[kt], wh.x, wh.y);
            }
            const int u0 = 8 * j + 2 * t;
            {
                float z0 = sigmoidf(az[0]);
                float r0 = sigmoidf(ar[0]);
                float h0 = z0 * fa.w + (1.f - z0) * tanh_fast(ah[0] + r0 * fa.z);
                float z1 = sigmoidf(az[2]);
                float r1 = sigmoidf(ar[2]);
                float h1 = z1 * fa.w + (1.f - z1) * tanh_fast(ah[2] + r1 * fa.z);
                hrow[g * 52 + u0] = h0;
                hrow[(g + 8) * 52 + u0] = h1;
            }
            {
                float z0 = sigmoidf(az[1]);
                float r0 = sigmoidf(ar[1]);
                float h0 = z0 * fb.w + (1.f - z0) * tanh_fast(ah[1] + r0 * fb.z);
                float z1 = sigmoidf(az[3]);
                float r1 = sigmoidf(ar[3]);
                float h1 = z1 * fb.w + (1.f - z1) * tanh_fast(ah[3] + r1 * fb.z);
                hrow[g * 52 + u0 + 1] = h0;
                hrow[(g + 8) * 52 + u0 + 1] = h1;
            }
        }
        __syncwarp();

        // head x-part: nt 18..20 (12 accumulators)
        float hx0[4] = {0, 0, 0, 0}, hx1[4] = {0, 0, 0, 0}, hx2[4] = {0, 0, 0, 0};
        #pragma unroll
        for (int kt = 0; kt < 4; kt++) {
            uint4 w0 = g_WB[(18 * 4 + kt) * 32 + lane];
            uint4 w1 = g_WB[(19 * 4 + kt) * 32 + lane];
            uint4 w2 = g_WB[(20 * 4 + kt) * 32 + lane];
            MMA(hx0, Ah[kt], w0.x, w0.y); MMA(hx0, Ah[kt], w0.z, w0.w); MMA(hx0, Al[kt], w0.x, w0.y);
            MMA(hx1, Ah[kt], w1.x, w1.y); MMA(hx1, Ah[kt], w1.z, w1.w); MMA(hx1, Al[kt], w1.x, w1.y);
            MMA(hx2, Ah[kt], w2.x, w2.y); MMA(hx2, Ah[kt], w2.z, w2.w); MMA(hx2, Al[kt], w2.x, w2.y);
        }

        ULL hg[3], hh[3];
        hg[0] = pk2(hx0[0], hx0[1]); hh[0] = pk2(hx0[2], hx0[3]);
        hg[1] = pk2(hx1[0], hx1[1]); hh[1] = pk2(hx1[2], hx1[3]);
        hg[2] = pk2(hx2[0], hx2[1]); hh[2] = pk2(hx2[2], hx2[3]);
        for (int u = 0; u < 48; u++) {
            float h0 = hrow[g * 52 + u], h1 = hrow[(g + 8) * 52 + u];
            ULL b0 = pk2(h0, h0), b1 = pk2(h1, h1);
            #pragma unroll
            for (int m = 0; m < 3; m++) {
                ULL w = *(const ULL*)(sDh + u * 24 + 8 * m + 2 * t);
                hg[m] = fma2(b0, w, hg[m]);
                hh[m] = fma2(b1, w, hh[m]);
            }
        }

        float o0 = 0.f, o1 = 0.f;
        #pragma unroll
        for (int m = 0; m < 3; m++) {
            int c = 8 * m + 2 * t;
            float d0 = Db[c], d1 = Db[c + 1], w0 = Ow[c], w1 = Ow[c + 1];
            float2 a = up2(hg[m]), bq = up2(hh[m]);
            o0 = fmaf(fmaxf(a.x + d0, 0.f), w0, o0);
            o0 = fmaf(fmaxf(a.y + d1, 0.f), w1, o0);
            o1 = fmaf(fmaxf(bq.x + d0, 0.f), w0, o1);
            o1 = fmaf(fmaxf(bq.y + d1, 0.f), w1, o1);
        }
        o0 += __shfl_xor_sync(0xffffffffu, o0, 1);
        o0 += __shfl_xor_sync(0xffffffffu, o0, 2);
        o1 += __shfl_xor_sync(0xffffffffu, o1, 1);
        o1 += __shfl_xor_sync(0xffffffffu, o1, 2);
        if (t == 0) {
            if (bA >= 0) out[bA] = sigmoidf(o0 + ob);
            if (bB >= 0) out[bB] = sigmoidf(o1 + ob);
        }

        const int win = g_winner[s];
        if (win >= 0 && t == 0) {
            if (bA == win || bB == win) {
                int r = (bA == win) ? g : g + 8;
                float4* os = (float4*)(out_state + s * 48);
                const float4* hr = (const float4*)(hrow + r * 52);
                #pragma unroll
                for (int m = 0; m < 12; m++) os[m] = hr[m];
            }
        }
        __syncwarp();
    }
}

extern "C" void kernel_launch(void* const* d_in, const int* in_sizes, int n_in,
                              void* d_out, int out_size) {
    const float* inputs = (const float*)d_in[0];
    const int*   ids    = (const int*)d_in[1];
    const float* state  = (const float*)d_in[2];
    const float* Wk     = (const float*)d_in[3];
    const float* Urec   = (const float*)d_in[4];
    const float* gbias  = (const float*)d_in[5];
    const float* Dw     = (const float*)d_in[6];
    const float* Db     = (const float*)d_in[7];
    const float* Ow     = (const float*)d_in[8];
    const float* Ob     = (const float*)d_in[9];

    const int B = in_sizes[0] / 32;
    const int S = in_sizes[2] / 48;

    float* out       = (float*)d_out;
    float* out_state = out + B;

    setup_kernel<<<S + 1 + BIN_CTAS, 256>>>(state, Urec, out_state, gbias, Wk, Dw, ids, B);
    scan_kernel<<<1, 1024>>>();
    tmap_kernel<<<S, 32>>>();
    main_kernel<<<888, 128>>>(inputs, gbias, Dw, Db, Ow, Ob, out, out_state);
}